// round 15
// baseline (speedup 1.0000x reference)
#include <cuda_runtime.h>

#define N_NEURONS 131072
#define NSTATES   32
#define CDIM      16
#define NBATCH    4
#define X_ELEMS   (NBATCH * N_NEURONS * NSTATES)   // 16777216
#define S_ELEMS   (N_NEURONS * NSTATES)            // 4194304

typedef unsigned long long u64;

// ---------------- encoder weights in constant memory (LDC.128 port) ----------------
__constant__ __align__(16) u64 cWenc2[CDIM * NSTATES / 2];   // [j][s-pair]: 16 u64/row, 128B-aligned rows

// ---------------- f32x2 packed helpers ----------------
__device__ __forceinline__ u64 pack2(float a, float b) {
    u64 r; asm("mov.b64 %0, {%1, %2};" : "=l"(r) : "f"(a), "f"(b)); return r;
}
__device__ __forceinline__ float2 unpack2(u64 v) {
    float2 f; asm("mov.b64 {%0, %1}, %2;" : "=f"(f.x), "=f"(f.y) : "l"(v)); return f;
}
__device__ __forceinline__ u64 fma2(u64 a, u64 b, u64 c) {
    u64 d; asm("fma.rn.f32x2 %0, %1, %2, %3;" : "=l"(d) : "l"(a), "l"(b), "l"(c)); return d;
}
__device__ __forceinline__ u64 mul2(u64 a, u64 b) {
    u64 d; asm("mul.rn.f32x2 %0, %1, %2;" : "=l"(d) : "l"(a), "l"(b)); return d;
}

// ---------------- tanh pieces (R10 hybrid, measured 23us / rel_err ~1e-5) ----------------
__device__ __forceinline__ u64 poly2(u64 x2, const u64* __restrict__ C) {
    u64 t2 = mul2(x2, x2);
    u64 p  = fma2(t2, C[0], C[1]);
    p = fma2(t2, p, C[2]);
    p = fma2(t2, p, C[3]);
    p = fma2(t2, p, C[4]);
    p = fma2(t2, p, C[5]);
    p = fma2(t2, p, C[6]);
    p = fma2(t2, p, C[7]);
    return mul2(p, x2);
}

__device__ __forceinline__ void make_coeffs(u64* C) {
    const float c[8] = { -0.001455834387f,  0.003592128037f, -0.008863235530f,
                          0.021869488537f, -0.053968253968f,  0.133333333333f,
                         -0.333333333333f,  1.0f };
    #pragma unroll
    for (int i = 0; i < 8; i++) C[i] = pack2(c[i], c[i]);
}

__device__ __forceinline__ float mufu_tanh(float x) {
    float t; asm("tanh.approx.f32 %0, %1;" : "=f"(t) : "f"(x)); return t;
}

__device__ __forceinline__ void tanh_s1_pair(float& a, float& b) {
    const float xa = a, xb = b;
    float ta = mufu_tanh(xa);
    float tb = mufu_tanh(xb);
    u64 x2 = pack2(xa, xb);
    u64 t2 = mul2(x2, x2);
    u64 p  = fma2(t2, pack2(-0.333333333f, -0.333333333f), pack2(1.0f, 1.0f));
    float2 pp = unpack2(mul2(p, x2));
    a = (fabsf(xa) >= 0.125f) ? ta : pp.x;
    b = (fabsf(xb) >= 0.125f) ? tb : pp.y;
}

__device__ __forceinline__ void tanh_s2_pair(float& a, float& b) {
    const float ya = a, yb = b;
    float2 s = unpack2(mul2(pack2(ya, yb), pack2(2.8853900817779268f, 2.8853900817779268f)));
    float ea, eb;
    asm("ex2.approx.ftz.f32 %0, %1;" : "=f"(ea) : "f"(s.x));
    asm("ex2.approx.ftz.f32 %0, %1;" : "=f"(eb) : "f"(s.y));
    float na = ea - 1.0f, da = ea + 1.0f;
    float nb = eb - 1.0f, db = eb + 1.0f;
    float ra, rb;
    asm("rcp.approx.ftz.f32 %0, %1;" : "=f"(ra) : "f"(da));
    asm("rcp.approx.ftz.f32 %0, %1;" : "=f"(rb) : "f"(db));
    float ta = na * ra;
    float tb = nb * rb;
    a = (fabsf(ya) >= 0.01f) ? ta : ya;
    b = (fabsf(yb) >= 0.01f) ? tb : yb;
}

__device__ __forceinline__ void tanh4_pair(float& a, float& b, const u64* __restrict__ C) {
    tanh_s1_pair(a, b);
    tanh_s2_pair(a, b);
    float2 f = unpack2(poly2(pack2(a, b), C)); a = f.x; b = f.y;
    f = unpack2(poly2(pack2(a, b), C));        a = f.x; b = f.y;
}

// =================== tanh kernel: 32 elems/thread ===================
#define TTPB 256
#define TANH_GRID (X_ELEMS / 32 / TTPB)   // 2048 blocks

__global__ void __launch_bounds__(TTPB)
tanh_kernel(const float4* __restrict__ xin, float4* __restrict__ xout)
{
    u64 C[8];
    make_coeffs(C);

    const int base = blockIdx.x * (TTPB * 8) + threadIdx.x;
    #pragma unroll
    for (int half = 0; half < 2; half++) {
        float4 v[4];
        #pragma unroll
        for (int k = 0; k < 4; k++) v[k] = xin[base + (half * 4 + k) * TTPB];
        #pragma unroll
        for (int k = 0; k < 4; k++) {
            tanh4_pair(v[k].x, v[k].y, C);
            tanh4_pair(v[k].z, v[k].w, C);
        }
        #pragma unroll
        for (int k = 0; k < 4; k++) xout[base + (half * 4 + k) * TTPB] = v[k];
    }
}

// =================== states kernel: enc const(LDC.128) / dec global(LDG.128 L1-hit) ===================
#define STPB 32

#define CE(arr, i, j) { float _hi = fmaxf(arr[i], arr[j]); \
                        float _lo = fminf(arr[i], arr[j]); \
                        arr[i] = _hi; arr[j] = _lo; }

#define SORT8(v) { \
    CE(v,0,1) CE(v,2,3) CE(v,4,5) CE(v,6,7) \
    CE(v,0,2) CE(v,1,3) CE(v,4,6) CE(v,5,7) \
    CE(v,1,2) CE(v,5,6) \
    CE(v,0,4) CE(v,1,5) CE(v,2,6) CE(v,3,7) \
    CE(v,2,4) CE(v,3,5) \
    CE(v,1,2) CE(v,3,4) CE(v,5,6) }

#define BSORT8(z) { \
    CE(z,0,4) CE(z,1,5) CE(z,2,6) CE(z,3,7) \
    CE(z,0,2) CE(z,1,3) CE(z,4,6) CE(z,5,7) \
    CE(z,0,1) CE(z,2,3) CE(z,4,5) CE(z,6,7) }

__global__ void __launch_bounds__(STPB, 24)   // 85-reg cap; up to 24 warps/SM
states_kernel(const float* __restrict__ ns,
              const float* __restrict__ benc,
              const float* __restrict__ Wdec,
              const float* __restrict__ bdec,
              float* __restrict__ sout)
{
    const int n = blockIdx.x * STPB + threadIdx.x;

    u64 st2[NSTATES / 2];     // packed current states (32 regs)
    u64 dotE2[CDIM / 2];      // compressed encoder recency dots (16 regs)
    {
        const u64* src = reinterpret_cast<const u64*>(ns) + (size_t)n * (NSTATES / 2);
        #pragma unroll
        for (int i = 0; i < NSTATES / 2; i++) {
            float2 f = unpack2(src[i]);
            // layer-0 sparsity mask (no-op later: survivors are 0 or >= 0.05)
            f.x = (fabsf(f.x) >= 0.01f) ? f.x : 0.0f;
            f.y = (fabsf(f.y) >= 0.01f) ? f.y : 0.0f;
            st2[i] = pack2(f.x, f.y);
        }
        #pragma unroll
        for (int i = 0; i < CDIM / 2; i++) dotE2[i] = 0ull;
    }

    const u64 K07 = pack2(0.7f, 0.7f);
    const ulonglong2* wdec = reinterpret_cast<const ulonglong2*>(Wdec);  // [s][j]: 4 u64x2 per row

    #pragma unroll 1
    for (int L = 0; L < 4; L++) {
        // 0.9 decay folded into the recency normalizer
        const float wscl = (L == 0) ? 0.9f
                         : (L == 1) ? (0.9f / 1.7f)
                         : (L == 2) ? (0.9f / 2.19f)
                         :            (0.9f / 2.533f);

        // ---- encoder (const weights, LDC.128): fresh = Wenc @ st ;
        //      dotE = 0.7*dotE + fresh ; h = relu(wscl*dotE + benc) ----
        u64 ph[CDIM / 2];
        #pragma unroll 2
        for (int j2 = 0; j2 < CDIM / 2; j2++) {
            float fr[2];
            #pragma unroll
            for (int q = 0; q < 2; q++) {
                const int j = 2 * j2 + q;
                const ulonglong2* w = reinterpret_cast<const ulonglong2*>(&cWenc2[j * 16]);
                u64 a = 0ull;
                #pragma unroll
                for (int k = 0; k < 8; k++) {
                    ulonglong2 wv = w[k];                 // LDC.128
                    a = fma2(st2[2*k+0], wv.x, a);
                    a = fma2(st2[2*k+1], wv.y, a);
                }
                float2 f = unpack2(a);
                fr[q] = f.x + f.y;
            }
            dotE2[j2] = fma2(dotE2[j2], K07, pack2(fr[0], fr[1]));
            float2 d = unpack2(dotE2[j2]);
            float h0 = fmaxf(fmaf(d.x, wscl, __ldg(&benc[2*j2+0])), 0.0f);
            float h1 = fmaxf(fmaf(d.y, wscl, __ldg(&benc[2*j2+1])), 0.0f);
            ph[j2] = pack2(h0, h1);
        }

        // ---- decoder (global weights, LDG.128 L1-resident): raw rec into st2 ----
        #pragma unroll 4
        for (int i = 0; i < NSTATES / 2; i++) {
            float o[2];
            #pragma unroll
            for (int q = 0; q < 2; q++) {
                const int s = 2 * i + q;
                u64 a = 0ull;
                #pragma unroll
                for (int k = 0; k < 4; k++) {
                    ulonglong2 wv = __ldg(&wdec[s * 4 + k]);   // LDG.128, L1 hit (2KB resident)
                    a = fma2(ph[2*k+0], wv.x, a);
                    a = fma2(ph[2*k+1], wv.y, a);
                }
                float2 f = unpack2(a);
                o[q] = f.x + f.y + __ldg(&bdec[s]);
            }
            st2[i] = pack2(o[0], o[1]);
        }

        // ---- T = max(8th-largest |rec|, 0.05): fuses importance + top-k masks ----
        float m[8], g[8];
        #pragma unroll
        for (int i = 0; i < 4; i++) {
            float2 f = unpack2(st2[i] & 0x7FFFFFFF7FFFFFFFull);
            m[2*i] = f.x; m[2*i+1] = f.y;
        }
        SORT8(m)
        #pragma unroll
        for (int gr = 1; gr < 4; gr++) {
            #pragma unroll
            for (int i = 0; i < 4; i++) {
                float2 f = unpack2(st2[gr*4 + i] & 0x7FFFFFFF7FFFFFFFull);
                g[2*i] = f.x; g[2*i+1] = f.y;
            }
            SORT8(g)
            #pragma unroll
            for (int i = 0; i < 8; i++) m[i] = fmaxf(m[i], g[7 - i]);
            BSORT8(m)
        }
        const float T = fmaxf(m[7], 0.05f);
        #pragma unroll
        for (int i = 0; i < NSTATES / 2; i++) {
            float2 f = unpack2(st2[i]);
            f.x = (fabsf(f.x) >= T) ? f.x : 0.0f;
            f.y = (fabsf(f.y) >= T) ? f.y : 0.0f;
            st2[i] = pack2(f.x, f.y);
        }
    }

    {
        ulonglong2* dst = reinterpret_cast<ulonglong2*>(sout) + (size_t)n * (NSTATES / 4);
        #pragma unroll
        for (int i = 0; i < NSTATES / 4; i++) {
            ulonglong2 v;
            v.x = st2[2*i+0];
            v.y = st2[2*i+1];
            dst[i] = v;
        }
    }
}

extern "C" void kernel_launch(void* const* d_in, const int* in_sizes, int n_in,
                              void* d_out, int out_size) {
    const float* x    = (const float*)d_in[0];
    const float* ns   = (const float*)d_in[1];
    const float* Wenc = (const float*)d_in[2];
    const float* benc = (const float*)d_in[3];
    const float* Wdec = (const float*)d_in[4];
    const float* bdec = (const float*)d_in[5];

    float* out  = (float*)d_out;
    float* xout = nullptr;
    float* sout = nullptr;
    if (out_size >= X_ELEMS + S_ELEMS) { xout = out; sout = out + X_ELEMS; }
    else if (out_size == S_ELEMS)      { sout = out; }
    else                               { xout = out; }

    if (xout)
        tanh_kernel<<<TANH_GRID, TTPB>>>(reinterpret_cast<const float4*>(x),
                                         reinterpret_cast<float4*>(xout));
    if (sout) {
        cudaMemcpyToSymbolAsync(cWenc2, Wenc, CDIM * NSTATES * sizeof(float), 0,
                                cudaMemcpyDeviceToDevice);
        states_kernel<<<N_NEURONS / STPB, STPB>>>(ns, benc, Wdec, bdec, sout);
    }
}

// round 16
// speedup vs baseline: 1.1085x; 1.1085x over previous
#include <cuda_runtime.h>

#define N_NEURONS 131072
#define NSTATES   32
#define CDIM      16
#define NBATCH    4
#define X_ELEMS   (NBATCH * N_NEURONS * NSTATES)   // 16777216
#define S_ELEMS   (N_NEURONS * NSTATES)            // 4194304

typedef unsigned long long u64;

// ---------------- both weight matrices in constant memory, 16B-aligned (LDC.128) ----------------
__constant__ __align__(16) u64 cWenc2[CDIM * NSTATES / 2];   // [j][s-pair]: 16 u64 (128B) per row
__constant__ __align__(16) u64 cWdec2[NSTATES * CDIM / 2];   // [s][j-pair]:  8 u64 (64B)  per row

// ---------------- f32x2 packed helpers ----------------
__device__ __forceinline__ u64 pack2(float a, float b) {
    u64 r; asm("mov.b64 %0, {%1, %2};" : "=l"(r) : "f"(a), "f"(b)); return r;
}
__device__ __forceinline__ float2 unpack2(u64 v) {
    float2 f; asm("mov.b64 {%0, %1}, %2;" : "=f"(f.x), "=f"(f.y) : "l"(v)); return f;
}
__device__ __forceinline__ u64 fma2(u64 a, u64 b, u64 c) {
    u64 d; asm("fma.rn.f32x2 %0, %1, %2, %3;" : "=l"(d) : "l"(a), "l"(b), "l"(c)); return d;
}
__device__ __forceinline__ u64 mul2(u64 a, u64 b) {
    u64 d; asm("mul.rn.f32x2 %0, %1, %2;" : "=l"(d) : "l"(a), "l"(b)); return d;
}

// ---------------- tanh pieces (R10 hybrid, measured 23us) ----------------
__device__ __forceinline__ u64 poly2(u64 x2, const u64* __restrict__ C) {
    u64 t2 = mul2(x2, x2);
    u64 p  = fma2(t2, C[0], C[1]);
    p = fma2(t2, p, C[2]);
    p = fma2(t2, p, C[3]);
    p = fma2(t2, p, C[4]);
    p = fma2(t2, p, C[5]);
    p = fma2(t2, p, C[6]);
    p = fma2(t2, p, C[7]);
    return mul2(p, x2);
}

__device__ __forceinline__ void make_coeffs(u64* C) {
    const float c[8] = { -0.001455834387f,  0.003592128037f, -0.008863235530f,
                          0.021869488537f, -0.053968253968f,  0.133333333333f,
                         -0.333333333333f,  1.0f };
    #pragma unroll
    for (int i = 0; i < 8; i++) C[i] = pack2(c[i], c[i]);
}

__device__ __forceinline__ float mufu_tanh(float x) {
    float t; asm("tanh.approx.f32 %0, %1;" : "=f"(t) : "f"(x)); return t;
}

__device__ __forceinline__ void tanh_s1_pair(float& a, float& b) {
    const float xa = a, xb = b;
    float ta = mufu_tanh(xa);
    float tb = mufu_tanh(xb);
    u64 x2 = pack2(xa, xb);
    u64 t2 = mul2(x2, x2);
    u64 p  = fma2(t2, pack2(-0.333333333f, -0.333333333f), pack2(1.0f, 1.0f));
    float2 pp = unpack2(mul2(p, x2));
    a = (fabsf(xa) >= 0.125f) ? ta : pp.x;
    b = (fabsf(xb) >= 0.125f) ? tb : pp.y;
}

__device__ __forceinline__ void tanh_s2_pair(float& a, float& b) {
    const float ya = a, yb = b;
    float2 s = unpack2(mul2(pack2(ya, yb), pack2(2.8853900817779268f, 2.8853900817779268f)));
    float ea, eb;
    asm("ex2.approx.ftz.f32 %0, %1;" : "=f"(ea) : "f"(s.x));
    asm("ex2.approx.ftz.f32 %0, %1;" : "=f"(eb) : "f"(s.y));
    float na = ea - 1.0f, da = ea + 1.0f;
    float nb = eb - 1.0f, db = eb + 1.0f;
    float ra, rb;
    asm("rcp.approx.ftz.f32 %0, %1;" : "=f"(ra) : "f"(da));
    asm("rcp.approx.ftz.f32 %0, %1;" : "=f"(rb) : "f"(db));
    float ta = na * ra;
    float tb = nb * rb;
    a = (fabsf(ya) >= 0.01f) ? ta : ya;
    b = (fabsf(yb) >= 0.01f) ? tb : yb;
}

__device__ __forceinline__ void tanh4_pair(float& a, float& b, const u64* __restrict__ C) {
    tanh_s1_pair(a, b);
    tanh_s2_pair(a, b);
    float2 f = unpack2(poly2(pack2(a, b), C)); a = f.x; b = f.y;
    f = unpack2(poly2(pack2(a, b), C));        a = f.x; b = f.y;
}

// =================== tanh kernel: 32 elems/thread ===================
#define TTPB 256
#define TANH_GRID (X_ELEMS / 32 / TTPB)   // 2048 blocks

__global__ void __launch_bounds__(TTPB)
tanh_kernel(const float4* __restrict__ xin, float4* __restrict__ xout)
{
    u64 C[8];
    make_coeffs(C);

    const int base = blockIdx.x * (TTPB * 8) + threadIdx.x;
    #pragma unroll
    for (int half = 0; half < 2; half++) {
        float4 v[4];
        #pragma unroll
        for (int k = 0; k < 4; k++) v[k] = xin[base + (half * 4 + k) * TTPB];
        #pragma unroll
        for (int k = 0; k < 4; k++) {
            tanh4_pair(v[k].x, v[k].y, C);
            tanh4_pair(v[k].z, v[k].w, C);
        }
        #pragma unroll
        for (int k = 0; k < 4; k++) xout[base + (half * 4 + k) * TTPB] = v[k];
    }
}

// =================== states kernel: all-const weights via LDC.128 ===================
#define STPB 32

#define CE(arr, i, j) { float _hi = fmaxf(arr[i], arr[j]); \
                        float _lo = fminf(arr[i], arr[j]); \
                        arr[i] = _hi; arr[j] = _lo; }

#define SORT8(v) { \
    CE(v,0,1) CE(v,2,3) CE(v,4,5) CE(v,6,7) \
    CE(v,0,2) CE(v,1,3) CE(v,4,6) CE(v,5,7) \
    CE(v,1,2) CE(v,5,6) \
    CE(v,0,4) CE(v,1,5) CE(v,2,6) CE(v,3,7) \
    CE(v,2,4) CE(v,3,5) \
    CE(v,1,2) CE(v,3,4) CE(v,5,6) }

#define BSORT8(z) { \
    CE(z,0,4) CE(z,1,5) CE(z,2,6) CE(z,3,7) \
    CE(z,0,2) CE(z,1,3) CE(z,4,6) CE(z,5,7) \
    CE(z,0,1) CE(z,2,3) CE(z,4,5) CE(z,6,7) }

__global__ void __launch_bounds__(STPB, 24)   // 85-reg cap; up to 24 warps/SM
states_kernel(const float* __restrict__ ns,
              const float* __restrict__ benc,
              const float* __restrict__ bdec,
              float* __restrict__ sout)
{
    const int n = blockIdx.x * STPB + threadIdx.x;

    u64 st2[NSTATES / 2];     // packed current states (32 regs)
    u64 dotE2[CDIM / 2];      // compressed encoder recency dots (16 regs)
    {
        const u64* src = reinterpret_cast<const u64*>(ns) + (size_t)n * (NSTATES / 2);
        #pragma unroll
        for (int i = 0; i < NSTATES / 2; i++) {
            float2 f = unpack2(src[i]);
            // layer-0 sparsity mask (no-op later: survivors are 0 or >= 0.05)
            f.x = (fabsf(f.x) >= 0.01f) ? f.x : 0.0f;
            f.y = (fabsf(f.y) >= 0.01f) ? f.y : 0.0f;
            st2[i] = pack2(f.x, f.y);
        }
        #pragma unroll
        for (int i = 0; i < CDIM / 2; i++) dotE2[i] = 0ull;
    }

    const u64 K07 = pack2(0.7f, 0.7f);

    #pragma unroll 1
    for (int L = 0; L < 4; L++) {
        // 0.9 decay folded into the recency normalizer
        const float wscl = (L == 0) ? 0.9f
                         : (L == 1) ? (0.9f / 1.7f)
                         : (L == 2) ? (0.9f / 2.19f)
                         :            (0.9f / 2.533f);

        // ---- encoder (const, LDC.128): fresh = Wenc @ st ;
        //      dotE = 0.7*dotE + fresh ; h = relu(wscl*dotE + benc) ----
        u64 ph[CDIM / 2];
        #pragma unroll 2
        for (int j2 = 0; j2 < CDIM / 2; j2++) {
            float fr[2];
            #pragma unroll
            for (int q = 0; q < 2; q++) {
                const int j = 2 * j2 + q;
                const ulonglong2* w = reinterpret_cast<const ulonglong2*>(&cWenc2[j * 16]);
                u64 a = 0ull;
                #pragma unroll
                for (int k = 0; k < 8; k++) {
                    ulonglong2 wv = w[k];                 // LDC.128
                    a = fma2(st2[2*k+0], wv.x, a);
                    a = fma2(st2[2*k+1], wv.y, a);
                }
                float2 f = unpack2(a);
                fr[q] = f.x + f.y;
            }
            dotE2[j2] = fma2(dotE2[j2], K07, pack2(fr[0], fr[1]));
            float2 d = unpack2(dotE2[j2]);
            float h0 = fmaxf(fmaf(d.x, wscl, __ldg(&benc[2*j2+0])), 0.0f);
            float h1 = fmaxf(fmaf(d.y, wscl, __ldg(&benc[2*j2+1])), 0.0f);
            ph[j2] = pack2(h0, h1);
        }

        // ---- decoder (const, LDC.128): raw rec into st2 ----
        #pragma unroll 4
        for (int i = 0; i < NSTATES / 2; i++) {
            float o[2];
            #pragma unroll
            for (int q = 0; q < 2; q++) {
                const int s = 2 * i + q;
                const ulonglong2* w = reinterpret_cast<const ulonglong2*>(&cWdec2[s * 8]);
                u64 a = 0ull;
                #pragma unroll
                for (int k = 0; k < 4; k++) {
                    ulonglong2 wv = w[k];                 // LDC.128
                    a = fma2(ph[2*k+0], wv.x, a);
                    a = fma2(ph[2*k+1], wv.y, a);
                }
                float2 f = unpack2(a);
                o[q] = f.x + f.y + __ldg(&bdec[s]);
            }
            st2[i] = pack2(o[0], o[1]);
        }

        // ---- T = max(8th-largest |rec|, 0.05): fuses importance + top-k masks ----
        float m[8], g[8];
        #pragma unroll
        for (int i = 0; i < 4; i++) {
            float2 f = unpack2(st2[i] & 0x7FFFFFFF7FFFFFFFull);
            m[2*i] = f.x; m[2*i+1] = f.y;
        }
        SORT8(m)
        #pragma unroll
        for (int gr = 1; gr < 4; gr++) {
            #pragma unroll
            for (int i = 0; i < 4; i++) {
                float2 f = unpack2(st2[gr*4 + i] & 0x7FFFFFFF7FFFFFFFull);
                g[2*i] = f.x; g[2*i+1] = f.y;
            }
            SORT8(g)
            #pragma unroll
            for (int i = 0; i < 8; i++) m[i] = fmaxf(m[i], g[7 - i]);
            BSORT8(m)
        }
        const float T = fmaxf(m[7], 0.05f);
        #pragma unroll
        for (int i = 0; i < NSTATES / 2; i++) {
            float2 f = unpack2(st2[i]);
            f.x = (fabsf(f.x) >= T) ? f.x : 0.0f;
            f.y = (fabsf(f.y) >= T) ? f.y : 0.0f;
            st2[i] = pack2(f.x, f.y);
        }
    }

    {
        ulonglong2* dst = reinterpret_cast<ulonglong2*>(sout) + (size_t)n * (NSTATES / 4);
        #pragma unroll
        for (int i = 0; i < NSTATES / 4; i++) {
            ulonglong2 v;
            v.x = st2[2*i+0];
            v.y = st2[2*i+1];
            dst[i] = v;
        }
    }
}

extern "C" void kernel_launch(void* const* d_in, const int* in_sizes, int n_in,
                              void* d_out, int out_size) {
    const float* x    = (const float*)d_in[0];
    const float* ns   = (const float*)d_in[1];
    const float* Wenc = (const float*)d_in[2];
    const float* benc = (const float*)d_in[3];
    const float* Wdec = (const float*)d_in[4];
    const float* bdec = (const float*)d_in[5];

    float* out  = (float*)d_out;
    float* xout = nullptr;
    float* sout = nullptr;
    if (out_size >= X_ELEMS + S_ELEMS) { xout = out; sout = out + X_ELEMS; }
    else if (out_size == S_ELEMS)      { sout = out; }
    else                               { xout = out; }

    if (sout) {
        cudaMemcpyToSymbolAsync(cWenc2, Wenc, CDIM * NSTATES * sizeof(float), 0,
                                cudaMemcpyDeviceToDevice);
        cudaMemcpyToSymbolAsync(cWdec2, Wdec, NSTATES * CDIM * sizeof(float), 0,
                                cudaMemcpyDeviceToDevice);
    }
    if (xout)
        tanh_kernel<<<TANH_GRID, TTPB>>>(reinterpret_cast<const float4*>(x),
                                         reinterpret_cast<float4*>(xout));
    if (sout)
        states_kernel<<<N_NEURONS / STPB, STPB>>>(ns, benc, bdec, sout);
}

// round 17
// speedup vs baseline: 1.1285x; 1.0180x over previous
#include <cuda_runtime.h>

#define N_NEURONS 131072
#define NSTATES   32
#define CDIM      16
#define NBATCH    4
#define X_ELEMS   (NBATCH * N_NEURONS * NSTATES)   // 16777216
#define S_ELEMS   (N_NEURONS * NSTATES)            // 4194304

typedef unsigned long long u64;

// ---------------- both weight matrices in constant memory, 16B-aligned (LDC.128) ----------------
__constant__ __align__(16) u64 cWenc2[CDIM * NSTATES / 2];   // [j][s-pair]: 16 u64 (128B) per row
__constant__ __align__(16) u64 cWdec2[NSTATES * CDIM / 2];   // [s][j-pair]:  8 u64 (64B)  per row

// ---------------- f32x2 packed helpers ----------------
__device__ __forceinline__ u64 pack2(float a, float b) {
    u64 r; asm("mov.b64 %0, {%1, %2};" : "=l"(r) : "f"(a), "f"(b)); return r;
}
__device__ __forceinline__ float2 unpack2(u64 v) {
    float2 f; asm("mov.b64 {%0, %1}, %2;" : "=f"(f.x), "=f"(f.y) : "l"(v)); return f;
}
__device__ __forceinline__ u64 fma2(u64 a, u64 b, u64 c) {
    u64 d; asm("fma.rn.f32x2 %0, %1, %2, %3;" : "=l"(d) : "l"(a), "l"(b), "l"(c)); return d;
}
__device__ __forceinline__ u64 mul2(u64 a, u64 b) {
    u64 d; asm("mul.rn.f32x2 %0, %1, %2;" : "=l"(d) : "l"(a), "l"(b)); return d;
}

// ---------------- tanh pieces (R10 hybrid, measured 23us) ----------------
__device__ __forceinline__ u64 poly2(u64 x2, const u64* __restrict__ C) {
    u64 t2 = mul2(x2, x2);
    u64 p  = fma2(t2, C[0], C[1]);
    p = fma2(t2, p, C[2]);
    p = fma2(t2, p, C[3]);
    p = fma2(t2, p, C[4]);
    p = fma2(t2, p, C[5]);
    p = fma2(t2, p, C[6]);
    p = fma2(t2, p, C[7]);
    return mul2(p, x2);
}

__device__ __forceinline__ void make_coeffs(u64* C) {
    const float c[8] = { -0.001455834387f,  0.003592128037f, -0.008863235530f,
                          0.021869488537f, -0.053968253968f,  0.133333333333f,
                         -0.333333333333f,  1.0f };
    #pragma unroll
    for (int i = 0; i < 8; i++) C[i] = pack2(c[i], c[i]);
}

__device__ __forceinline__ float mufu_tanh(float x) {
    float t; asm("tanh.approx.f32 %0, %1;" : "=f"(t) : "f"(x)); return t;
}

__device__ __forceinline__ void tanh_s1_pair(float& a, float& b) {
    const float xa = a, xb = b;
    float ta = mufu_tanh(xa);
    float tb = mufu_tanh(xb);
    u64 x2 = pack2(xa, xb);
    u64 t2 = mul2(x2, x2);
    u64 p  = fma2(t2, pack2(-0.333333333f, -0.333333333f), pack2(1.0f, 1.0f));
    float2 pp = unpack2(mul2(p, x2));
    a = (fabsf(xa) >= 0.125f) ? ta : pp.x;
    b = (fabsf(xb) >= 0.125f) ? tb : pp.y;
}

__device__ __forceinline__ void tanh_s2_pair(float& a, float& b) {
    const float ya = a, yb = b;
    float2 s = unpack2(mul2(pack2(ya, yb), pack2(2.8853900817779268f, 2.8853900817779268f)));
    float ea, eb;
    asm("ex2.approx.ftz.f32 %0, %1;" : "=f"(ea) : "f"(s.x));
    asm("ex2.approx.ftz.f32 %0, %1;" : "=f"(eb) : "f"(s.y));
    float na = ea - 1.0f, da = ea + 1.0f;
    float nb = eb - 1.0f, db = eb + 1.0f;
    float ra, rb;
    asm("rcp.approx.ftz.f32 %0, %1;" : "=f"(ra) : "f"(da));
    asm("rcp.approx.ftz.f32 %0, %1;" : "=f"(rb) : "f"(db));
    float ta = na * ra;
    float tb = nb * rb;
    a = (fabsf(ya) >= 0.01f) ? ta : ya;
    b = (fabsf(yb) >= 0.01f) ? tb : yb;
}

__device__ __forceinline__ void tanh4_pair(float& a, float& b, const u64* __restrict__ C) {
    tanh_s1_pair(a, b);
    tanh_s2_pair(a, b);
    float2 f = unpack2(poly2(pack2(a, b), C)); a = f.x; b = f.y;
    f = unpack2(poly2(pack2(a, b), C));        a = f.x; b = f.y;
}

// =================== tanh kernel: 32 elems/thread ===================
#define TTPB 256
#define TANH_GRID (X_ELEMS / 32 / TTPB)   // 2048 blocks

__global__ void __launch_bounds__(TTPB)
tanh_kernel(const float4* __restrict__ xin, float4* __restrict__ xout)
{
    u64 C[8];
    make_coeffs(C);

    const int base = blockIdx.x * (TTPB * 8) + threadIdx.x;
    #pragma unroll
    for (int half = 0; half < 2; half++) {
        float4 v[4];
        #pragma unroll
        for (int k = 0; k < 4; k++) v[k] = xin[base + (half * 4 + k) * TTPB];
        #pragma unroll
        for (int k = 0; k < 4; k++) {
            tanh4_pair(v[k].x, v[k].y, C);
            tanh4_pair(v[k].z, v[k].w, C);
        }
        #pragma unroll
        for (int k = 0; k < 4; k++) xout[base + (half * 4 + k) * TTPB] = v[k];
    }
}

// =================== states kernel: all-const LDC.128, split chains, 28 blk/SM ===================
#define STPB 32

#define CE(arr, i, j) { float _hi = fmaxf(arr[i], arr[j]); \
                        float _lo = fminf(arr[i], arr[j]); \
                        arr[i] = _hi; arr[j] = _lo; }

#define SORT8(v) { \
    CE(v,0,1) CE(v,2,3) CE(v,4,5) CE(v,6,7) \
    CE(v,0,2) CE(v,1,3) CE(v,4,6) CE(v,5,7) \
    CE(v,1,2) CE(v,5,6) \
    CE(v,0,4) CE(v,1,5) CE(v,2,6) CE(v,3,7) \
    CE(v,2,4) CE(v,3,5) \
    CE(v,1,2) CE(v,3,4) CE(v,5,6) }

#define BSORT8(z) { \
    CE(z,0,4) CE(z,1,5) CE(z,2,6) CE(z,3,7) \
    CE(z,0,2) CE(z,1,3) CE(z,4,6) CE(z,5,7) \
    CE(z,0,1) CE(z,2,3) CE(z,4,5) CE(z,6,7) }

__global__ void __launch_bounds__(STPB, 28)   // 73-reg cap; up to 28 warps/SM
states_kernel(const float* __restrict__ ns,
              const float* __restrict__ benc,
              const float* __restrict__ bdec,
              float* __restrict__ sout)
{
    const int n = blockIdx.x * STPB + threadIdx.x;

    u64 st2[NSTATES / 2];     // packed current states (32 regs)
    u64 dotE2[CDIM / 2];      // compressed encoder recency dots (16 regs)
    {
        const u64* src = reinterpret_cast<const u64*>(ns) + (size_t)n * (NSTATES / 2);
        #pragma unroll
        for (int i = 0; i < NSTATES / 2; i++) {
            float2 f = unpack2(src[i]);
            // layer-0 sparsity mask (no-op later: survivors are 0 or >= 0.05)
            f.x = (fabsf(f.x) >= 0.01f) ? f.x : 0.0f;
            f.y = (fabsf(f.y) >= 0.01f) ? f.y : 0.0f;
            st2[i] = pack2(f.x, f.y);
        }
        #pragma unroll
        for (int i = 0; i < CDIM / 2; i++) dotE2[i] = 0ull;
    }

    const u64 K07 = pack2(0.7f, 0.7f);

    #pragma unroll 1
    for (int L = 0; L < 4; L++) {
        // 0.9 decay folded into the recency normalizer
        const float wscl = (L == 0) ? 0.9f
                         : (L == 1) ? (0.9f / 1.7f)
                         : (L == 2) ? (0.9f / 2.19f)
                         :            (0.9f / 2.533f);

        // ---- encoder (const, LDC.128), 2 split accumulator chains per output ----
        u64 ph[CDIM / 2];
        #pragma unroll 2
        for (int j2 = 0; j2 < CDIM / 2; j2++) {
            float fr[2];
            #pragma unroll
            for (int q = 0; q < 2; q++) {
                const int j = 2 * j2 + q;
                const ulonglong2* w = reinterpret_cast<const ulonglong2*>(&cWenc2[j * 16]);
                u64 a = 0ull, b = 0ull;        // independent chains (depth 8 each)
                #pragma unroll
                for (int k = 0; k < 8; k++) {
                    ulonglong2 wv = w[k];      // LDC.128
                    a = fma2(st2[2*k+0], wv.x, a);
                    b = fma2(st2[2*k+1], wv.y, b);
                }
                float2 fa = unpack2(a);
                float2 fb = unpack2(b);
                fr[q] = (fa.x + fa.y) + (fb.x + fb.y);
            }
            dotE2[j2] = fma2(dotE2[j2], K07, pack2(fr[0], fr[1]));
            float2 d = unpack2(dotE2[j2]);
            float h0 = fmaxf(fmaf(d.x, wscl, __ldg(&benc[2*j2+0])), 0.0f);
            float h1 = fmaxf(fmaf(d.y, wscl, __ldg(&benc[2*j2+1])), 0.0f);
            ph[j2] = pack2(h0, h1);
        }

        // ---- decoder (const, LDC.128), 2 split chains per output ----
        #pragma unroll 4
        for (int i = 0; i < NSTATES / 2; i++) {
            float o[2];
            #pragma unroll
            for (int q = 0; q < 2; q++) {
                const int s = 2 * i + q;
                const ulonglong2* w = reinterpret_cast<const ulonglong2*>(&cWdec2[s * 8]);
                u64 a = 0ull, b = 0ull;        // independent chains (depth 4 each)
                #pragma unroll
                for (int k = 0; k < 4; k++) {
                    ulonglong2 wv = w[k];      // LDC.128
                    a = fma2(ph[2*k+0], wv.x, a);
                    b = fma2(ph[2*k+1], wv.y, b);
                }
                float2 fa = unpack2(a);
                float2 fb = unpack2(b);
                o[q] = (fa.x + fa.y) + (fb.x + fb.y) + __ldg(&bdec[s]);
            }
            st2[i] = pack2(o[0], o[1]);
        }

        // ---- T = max(8th-largest |rec|, 0.05): fuses importance + top-k masks ----
        float m[8], g[8];
        #pragma unroll
        for (int i = 0; i < 4; i++) {
            float2 f = unpack2(st2[i] & 0x7FFFFFFF7FFFFFFFull);
            m[2*i] = f.x; m[2*i+1] = f.y;
        }
        SORT8(m)
        #pragma unroll
        for (int gr = 1; gr < 4; gr++) {
            #pragma unroll
            for (int i = 0; i < 4; i++) {
                float2 f = unpack2(st2[gr*4 + i] & 0x7FFFFFFF7FFFFFFFull);
                g[2*i] = f.x; g[2*i+1] = f.y;
            }
            SORT8(g)
            #pragma unroll
            for (int i = 0; i < 8; i++) m[i] = fmaxf(m[i], g[7 - i]);
            BSORT8(m)
        }
        const float T = fmaxf(m[7], 0.05f);
        #pragma unroll
        for (int i = 0; i < NSTATES / 2; i++) {
            float2 f = unpack2(st2[i]);
            f.x = (fabsf(f.x) >= T) ? f.x : 0.0f;
            f.y = (fabsf(f.y) >= T) ? f.y : 0.0f;
            st2[i] = pack2(f.x, f.y);
        }
    }

    {
        ulonglong2* dst = reinterpret_cast<ulonglong2*>(sout) + (size_t)n * (NSTATES / 4);
        #pragma unroll
        for (int i = 0; i < NSTATES / 4; i++) {
            ulonglong2 v;
            v.x = st2[2*i+0];
            v.y = st2[2*i+1];
            dst[i] = v;
        }
    }
}

extern "C" void kernel_launch(void* const* d_in, const int* in_sizes, int n_in,
                              void* d_out, int out_size) {
    const float* x    = (const float*)d_in[0];
    const float* ns   = (const float*)d_in[1];
    const float* Wenc = (const float*)d_in[2];
    const float* benc = (const float*)d_in[3];
    const float* Wdec = (const float*)d_in[4];
    const float* bdec = (const float*)d_in[5];

    float* out  = (float*)d_out;
    float* xout = nullptr;
    float* sout = nullptr;
    if (out_size >= X_ELEMS + S_ELEMS) { xout = out; sout = out + X_ELEMS; }
    else if (out_size == S_ELEMS)      { sout = out; }
    else                               { xout = out; }

    // R12 ordering: tanh first (hides memcpy node overhead), then const uploads, then states
    if (xout)
        tanh_kernel<<<TANH_GRID, TTPB>>>(reinterpret_cast<const float4*>(x),
                                         reinterpret_cast<float4*>(xout));
    if (sout) {
        cudaMemcpyToSymbolAsync(cWenc2, Wenc, CDIM * NSTATES * sizeof(float), 0,
                                cudaMemcpyDeviceToDevice);
        cudaMemcpyToSymbolAsync(cWdec2, Wdec, NSTATES * CDIM * sizeof(float), 0,
                                cudaMemcpyDeviceToDevice);
        states_kernel<<<N_NEURONS / STPB, STPB>>>(ns, benc, bdec, sout);
    }
}